// round 16
// baseline (speedup 1.0000x reference)
#include <cuda_runtime.h>
#include <cstdint>

#define Zdim 41
#define Ydim 1024
#define Xdim 1024
#define NVOX (Zdim * Ydim * Xdim)      // 42,991,616
#define NWORDS (NVOX / 32)             // 1,343,488
#define C_IN 32
#define C_OUT 64
#define KVOL 27
#define KCENTER 13
#define MAXN 300000
#define TILE 96                        // points per tile (96*8=768 float4)
#define CBLK 384                       // center threads per block (12 warps)

// Dense index grid: validity gated by g_bitmap (wiped each launch); the grid
// itself is never cleared, so stale entries are never read.
__device__ int      g_grid[NVOX];
__device__ unsigned g_bitmap[NWORDS];
__device__ int      g_npairs;
__device__ int2     g_pairs[MAXN * 8];

// High-priority side stream for center: its 148 blocks land 1-per-SM using
// ~47k of 65k regs, leaving room for the small chain blocks to co-reside
// and consume center's idle issue slots. Static-init host resources only.
static cudaStream_t g_s1;
static cudaEvent_t  g_ev_fork, g_ev_join;
namespace {
struct StreamInit {
    StreamInit() {
        int leastP = 0, greatestP = 0;
        cudaDeviceGetStreamPriorityRange(&leastP, &greatestP);
        cudaStreamCreateWithPriority(&g_s1, cudaStreamNonBlocking, greatestP);
        cudaEventCreateWithFlags(&g_ev_fork, cudaEventDisableTiming);
        cudaEventCreateWithFlags(&g_ev_join, cudaEventDisableTiming);
    }
};
StreamInit g_stream_init;
}

__global__ void clear_bitmap_kernel() {
    int i = blockIdx.x * blockDim.x + threadIdx.x;
    if (i == 0) g_npairs = 0;
    if (i * 4 < NWORDS) ((uint4*)g_bitmap)[i] = make_uint4(0, 0, 0, 0);
}

__global__ void scatter_kernel(const int* __restrict__ idx, int n) {
    int i = blockIdx.x * blockDim.x + threadIdx.x;
    if (i >= n) return;
    int4 v = ((const int4*)idx)[i];
    unsigned lin = (unsigned)v.y * (Ydim * Xdim) + (unsigned)v.z * Xdim + (unsigned)v.w;
    g_grid[lin] = i;
    atomicOr(&g_bitmap[lin >> 5], 1u << (lin & 31));
}

// Symmetric probing (thread = (point, group); 5 groups cover the 13 k<13
// offsets; each hit emits pair + mirror). Warp-aggregated emission.
__global__ void probe_kernel(const int* __restrict__ idx, int n) {
    int t = blockIdx.x * blockDim.x + threadIdx.x;
    int lane = threadIdx.x & 31;
    bool valid = t < n * 5;

    int kk[3];
    int nbv[3];
    int cnt = 0;
    int i = 0;

    if (valid) {
        i = t / 5;
        int g = t - i * 5;
        int4 v = ((const int4*)idx)[i];

        int dz = (g < 3) ? -1 : 0;       // groups: (-1,-1) (-1,0) (-1,1) (0,-1) (0,0)
        int dy = (g < 3) ? (g - 1) : (g - 4);
        int nz = v.y + dz;
        int ny = v.z + dy;
        if ((unsigned)nz < Zdim && (unsigned)ny < Ydim) {
            unsigned rowbase = ((unsigned)nz * Ydim + (unsigned)ny) * Xdim;
            int x = v.w;
            unsigned lin0 = rowbase + (unsigned)x;
            unsigned w0   = g_bitmap[lin0 >> 5];

            int kbase = (dz + 1) * 9 + (dy + 1) * 3;
            int dxhi = (g == 4) ? -1 : 1;

            #pragma unroll
            for (int dx = -1; dx <= 1; ++dx) {
                if (dx > dxhi) break;
                int nx = x + dx;
                if ((unsigned)nx >= Xdim) continue;
                unsigned lin = rowbase + (unsigned)nx;
                unsigned word = ((lin >> 5) == (lin0 >> 5)) ? w0 : g_bitmap[lin >> 5];
                if ((word >> (lin & 31)) & 1u) {
                    kk[cnt]  = kbase + dx + 1;
                    nbv[cnt] = g_grid[lin];          // rare
                    ++cnt;
                }
            }
        }
    }

    unsigned pre = (unsigned)cnt;
    #pragma unroll
    for (int d = 1; d < 32; d <<= 1) {
        unsigned v = __shfl_up_sync(0xffffffffu, pre, d);
        if (lane >= d) pre += v;
    }
    unsigned warptotal = __shfl_sync(0xffffffffu, pre, 31);
    unsigned excl = pre - (unsigned)cnt;

    unsigned base = 0;
    if (lane == 31 && warptotal)
        base = atomicAdd(&g_npairs, 2 * (int)warptotal);
    base = __shfl_sync(0xffffffffu, base, 31);

    for (int j = 0; j < cnt; ++j) {
        int pos = (int)base + 2 * ((int)excl + j);
        int k  = kk[j];
        int nb = nbv[j];
        g_pairs[pos]     = make_int2((i  << 5) | k,        nb);
        g_pairs[pos + 1] = make_int2((nb << 5) | (26 - k), i);
    }
}

__device__ __forceinline__ void fma2(unsigned long long& acc, float f,
                                     unsigned long long wv) {
    unsigned long long fv2;
    asm("mov.b64 %0, {%1, %1};" : "=l"(fv2) : "f"(f));
    asm("fma.rn.f32x2 %0, %1, %2, %3;" : "=l"(acc) : "l"(fv2), "l"(wv), "l"(acc));
}

// Center matvec, software-pipelined persistent form. 384 threads (12 warps)
// per block, ONE block per SM (~47k/65k regs) -- fast enough to be the
// short-ish long pole while chain blocks co-reside in the leftover RF.
__global__ void __launch_bounds__(CBLK) center_kernel(
    const float* __restrict__ feat, const float* __restrict__ w,
    float* __restrict__ out, int n)
{
    __shared__ float4 sf[2][TILE * (C_IN / 4)];    // 2 x 12 KB

    int tid   = threadIdx.x;
    int lane  = tid & 31;
    int wslot = tid >> 5;                          // 0..11

    const float* w13 = w + KCENTER * C_IN * C_OUT;
    unsigned long long wreg[C_IN];
    #pragma unroll
    for (int c = 0; c < C_IN; ++c)
        wreg[c] = ((const unsigned long long*)w13)[c * 32 + lane];

    const float4* featv = (const float4*)feat;
    long maxf4 = (long)n * (C_IN / 4) - 1;
    int ntiles = (n + TILE - 1) / TILE;

    int t = blockIdx.x;
    float4 r0, r1;
    if (t < ntiles) {
        long base = (long)t * (TILE * C_IN / 4);
        long i0 = base + tid;        if (i0 > maxf4) i0 = maxf4;
        long i1 = base + tid + CBLK; if (i1 > maxf4) i1 = maxf4;
        r0 = featv[i0];
        r1 = featv[i1];
    }

    int buf = 0;
    for (; t < ntiles; t += gridDim.x) {
        sf[buf][tid]        = r0;
        sf[buf][tid + CBLK] = r1;
        __syncthreads();

        int tn = t + gridDim.x;
        if (tn < ntiles) {
            long base = (long)tn * (TILE * C_IN / 4);
            long i0 = base + tid;        if (i0 > maxf4) i0 = maxf4;
            long i1 = base + tid + CBLK; if (i1 > maxf4) i1 = maxf4;
            r0 = featv[i0];
            r1 = featv[i1];
        }

        int p0 = wslot * 8;                        // 12 warps x 8 points = 96
        #pragma unroll
        for (int pp = 0; pp < 8; ++pp) {
            int i = t * TILE + p0 + pp;
            if (i >= n) break;
            const float4* frow = &sf[buf][(p0 + pp) * (C_IN / 4)];
            unsigned long long acc0, acc1, acc2, acc3;
            asm("mov.b64 %0, {%1, %1};" : "=l"(acc0) : "f"(0.0f));
            asm("mov.b64 %0, {%1, %1};" : "=l"(acc1) : "f"(0.0f));
            asm("mov.b64 %0, {%1, %1};" : "=l"(acc2) : "f"(0.0f));
            asm("mov.b64 %0, {%1, %1};" : "=l"(acc3) : "f"(0.0f));
            #pragma unroll
            for (int c4 = 0; c4 < C_IN / 4; ++c4) {
                float4 fv = frow[c4];              // broadcast LDS.128
                fma2(acc0, fv.x, wreg[c4 * 4 + 0]);
                fma2(acc1, fv.y, wreg[c4 * 4 + 1]);
                fma2(acc2, fv.z, wreg[c4 * 4 + 2]);
                fma2(acc3, fv.w, wreg[c4 * 4 + 3]);
            }
            unsigned long long s01, s23, s;
            asm("add.rn.f32x2 %0, %1, %2;" : "=l"(s01) : "l"(acc0), "l"(acc1));
            asm("add.rn.f32x2 %0, %1, %2;" : "=l"(s23) : "l"(acc2), "l"(acc3));
            asm("add.rn.f32x2 %0, %1, %2;" : "=l"(s)   : "l"(s01),  "l"(s23));
            ((unsigned long long*)out)[(size_t)i * 32 + lane] = s;   // STG.64
        }
        __syncthreads();
        buf ^= 1;
    }
}

// Rare neighbor contributions. 2 pairs/warp-iteration; ALL 16 feature
// float4 loads preloaded into registers before any FMA (MLP=16).
__global__ void __launch_bounds__(128, 4) pairs_kernel(
    const float* __restrict__ feat,
    const float* __restrict__ w,
    float* __restrict__ out)
{
    int lane   = threadIdx.x & 31;
    int warp_g = (blockIdx.x * blockDim.x + threadIdx.x) >> 5;
    int nwarps = (gridDim.x * blockDim.x) >> 5;
    int np = g_npairs;

    for (int p = warp_g * 2; p < np; p += nwarps * 2) {
        int4 pq = ((const int4*)g_pairs)[p >> 1];
        bool has1 = (p + 1) < np;

        const float4* f0v = (const float4*)(feat + (size_t)pq.y * C_IN);
        const float4* f1v = (const float4*)(feat + (size_t)(has1 ? pq.w : pq.y) * C_IN);

        float4 f0[8], f1[8];
        #pragma unroll
        for (int c4 = 0; c4 < 8; ++c4) f0[c4] = f0v[c4];
        #pragma unroll
        for (int c4 = 0; c4 < 8; ++c4) f1[c4] = f1v[c4];

        const unsigned long long* wk0 =
            (const unsigned long long*)(w + (size_t)(pq.x & 31) * C_IN * C_OUT);
        const unsigned long long* wk1 =
            (const unsigned long long*)(w + (size_t)(pq.z & 31) * C_IN * C_OUT);

        unsigned long long a0, a1, b0, b1;
        asm("mov.b64 %0, {%1, %1};" : "=l"(a0) : "f"(0.0f));
        asm("mov.b64 %0, {%1, %1};" : "=l"(a1) : "f"(0.0f));
        asm("mov.b64 %0, {%1, %1};" : "=l"(b0) : "f"(0.0f));
        asm("mov.b64 %0, {%1, %1};" : "=l"(b1) : "f"(0.0f));

        #pragma unroll
        for (int c4 = 0; c4 < 8; ++c4) {
            fma2(a0, f0[c4].x, wk0[(c4 * 4 + 0) * 32 + lane]);
            fma2(a1, f0[c4].y, wk0[(c4 * 4 + 1) * 32 + lane]);
            fma2(a0, f0[c4].z, wk0[(c4 * 4 + 2) * 32 + lane]);
            fma2(a1, f0[c4].w, wk0[(c4 * 4 + 3) * 32 + lane]);
            fma2(b0, f1[c4].x, wk1[(c4 * 4 + 0) * 32 + lane]);
            fma2(b1, f1[c4].y, wk1[(c4 * 4 + 1) * 32 + lane]);
            fma2(b0, f1[c4].z, wk1[(c4 * 4 + 2) * 32 + lane]);
            fma2(b1, f1[c4].w, wk1[(c4 * 4 + 3) * 32 + lane]);
        }

        unsigned long long sa, sb;
        asm("add.rn.f32x2 %0, %1, %2;" : "=l"(sa) : "l"(a0), "l"(a1));
        asm("add.rn.f32x2 %0, %1, %2;" : "=l"(sb) : "l"(b0), "l"(b1));
        float sa0, sa1, sb0, sb1;
        asm("mov.b64 {%0, %1}, %2;" : "=f"(sa0), "=f"(sa1) : "l"(sa));
        asm("mov.b64 {%0, %1}, %2;" : "=f"(sb0), "=f"(sb1) : "l"(sb));

        int i0 = pq.x >> 5;
        atomicAdd(&out[(size_t)i0 * C_OUT + 2 * lane],     sa0);
        atomicAdd(&out[(size_t)i0 * C_OUT + 2 * lane + 1], sa1);
        if (has1) {
            int i1 = pq.z >> 5;
            atomicAdd(&out[(size_t)i1 * C_OUT + 2 * lane],     sb0);
            atomicAdd(&out[(size_t)i1 * C_OUT + 2 * lane + 1], sb1);
        }
    }
}

extern "C" void kernel_launch(void* const* d_in, const int* in_sizes, int n_in,
                              void* d_out, int out_size) {
    const float* feat = (const float*)d_in[0];
    const int*   idx  = (const int*)d_in[1];
    const float* w    = (const float*)d_in[2];
    float* out = (float*)d_out;

    int n = in_sizes[0] / C_IN;

    // Fork: center on high-priority side stream, one 12-warp block per SM;
    // chain blocks co-reside in the leftover register file.
    cudaEventRecord(g_ev_fork, 0);
    cudaStreamWaitEvent(g_s1, g_ev_fork, 0);
    center_kernel<<<148, CBLK, 0, g_s1>>>(feat, w, out, n);
    cudaEventRecord(g_ev_join, g_s1);

    clear_bitmap_kernel<<<(NWORDS / 4 + 255) / 256, 256>>>();
    scatter_kernel<<<(n + 255) / 256, 256>>>(idx, n);
    probe_kernel<<<(n * 5 + 255) / 256, 256>>>(idx, n);

    // Join: pairs needs both probe's pair list and center's stores.
    cudaStreamWaitEvent(0, g_ev_join, 0);
    pairs_kernel<<<1184, 128>>>(feat, w, out);
}

// round 17
// speedup vs baseline: 1.0291x; 1.0291x over previous
#include <cuda_runtime.h>
#include <cstdint>

#define Zdim 41
#define Ydim 1024
#define Xdim 1024
#define NVOX (Zdim * Ydim * Xdim)      // 42,991,616
#define NWORDS (NVOX / 32)             // 1,343,488
#define C_IN 32
#define C_OUT 64
#define KVOL 27
#define KCENTER 13
#define MAXN 300000
#define TILE 64

// Dense index grid: validity gated by g_bitmap (wiped each launch); the grid
// itself is never cleared, so stale entries are never read.
__device__ int      g_grid[NVOX];
__device__ unsigned g_bitmap[NWORDS];
__device__ int      g_npairs;
__device__ int2     g_pairs[MAXN * 8];

// High-priority side stream: center's 148 blocks land 1-per-SM (half the RF
// each) so the small chain blocks co-reside and use center's idle issue
// slots. Static-init host resources only.
static cudaStream_t g_s1;
static cudaEvent_t  g_ev_fork, g_ev_join;
namespace {
struct StreamInit {
    StreamInit() {
        int leastP = 0, greatestP = 0;
        cudaDeviceGetStreamPriorityRange(&leastP, &greatestP);
        cudaStreamCreateWithPriority(&g_s1, cudaStreamNonBlocking, greatestP);
        cudaEventCreateWithFlags(&g_ev_fork, cudaEventDisableTiming);
        cudaEventCreateWithFlags(&g_ev_join, cudaEventDisableTiming);
    }
};
StreamInit g_stream_init;
}

__global__ void clear_bitmap_kernel() {
    int i = blockIdx.x * blockDim.x + threadIdx.x;
    if (i == 0) g_npairs = 0;
    if (i * 4 < NWORDS) ((uint4*)g_bitmap)[i] = make_uint4(0, 0, 0, 0);
}

__global__ void scatter_kernel(const int* __restrict__ idx, int n) {
    int i = blockIdx.x * blockDim.x + threadIdx.x;
    if (i >= n) return;
    int4 v = ((const int4*)idx)[i];
    unsigned lin = (unsigned)v.y * (Ydim * Xdim) + (unsigned)v.z * Xdim + (unsigned)v.w;
    g_grid[lin] = i;
    atomicOr(&g_bitmap[lin >> 5], 1u << (lin & 31));
}

// Symmetric probing (thread = (point, group); 5 groups cover the 13 k<13
// offsets; each hit emits pair + mirror). Warp-aggregated emission.
// NEW: a warp spans <=8 distinct points; lanes 0-7 load those idx records
// (8 LDG.128/warp instead of 32) and 3 SHFLs distribute z/y/x to all lanes
// -- cuts probe's LDG count ~35% (LSU-floor bound).
__global__ void probe_kernel(const int* __restrict__ idx, int n) {
    int lane    = threadIdx.x & 31;
    int warp_t0 = (int)(blockIdx.x * blockDim.x) + ((int)threadIdx.x & ~31);
    int t       = warp_t0 + lane;
    bool valid  = t < n * 5;

    // distribute idx: warp covers points [i_first, i_first+7]
    int i_first = warp_t0 / 5;
    int4 myidx  = make_int4(0, 0, 0, 0);
    int iload   = i_first + lane;
    if (lane < 8 && iload < n) myidx = ((const int4*)idx)[iload];

    int i = t / 5;
    int g = t - i * 5;
    int delta = i - i_first;          // 0..7
    int vy = __shfl_sync(0xffffffffu, myidx.y, delta);
    int vz = __shfl_sync(0xffffffffu, myidx.z, delta);
    int vx = __shfl_sync(0xffffffffu, myidx.w, delta);

    int kk[3];
    int nbv[3];
    int cnt = 0;

    if (valid) {
        int dz = (g < 3) ? -1 : 0;    // groups: (-1,-1) (-1,0) (-1,1) (0,-1) (0,0)
        int dy = (g < 3) ? (g - 1) : (g - 4);
        int nz = vy + dz;
        int ny = vz + dy;
        if ((unsigned)nz < Zdim && (unsigned)ny < Ydim) {
            unsigned rowbase = ((unsigned)nz * Ydim + (unsigned)ny) * Xdim;
            int x = vx;
            unsigned lin0 = rowbase + (unsigned)x;
            unsigned w0   = g_bitmap[lin0 >> 5];

            int kbase = (dz + 1) * 9 + (dy + 1) * 3;
            int dxhi = (g == 4) ? -1 : 1;

            #pragma unroll
            for (int dx = -1; dx <= 1; ++dx) {
                if (dx > dxhi) break;
                int nx = x + dx;
                if ((unsigned)nx >= Xdim) continue;
                unsigned lin = rowbase + (unsigned)nx;
                unsigned word = ((lin >> 5) == (lin0 >> 5)) ? w0 : g_bitmap[lin >> 5];
                if ((word >> (lin & 31)) & 1u) {
                    kk[cnt]  = kbase + dx + 1;
                    nbv[cnt] = g_grid[lin];          // rare
                    ++cnt;
                }
            }
        }
    }

    unsigned pre = (unsigned)cnt;
    #pragma unroll
    for (int d = 1; d < 32; d <<= 1) {
        unsigned v = __shfl_up_sync(0xffffffffu, pre, d);
        if (lane >= d) pre += v;
    }
    unsigned warptotal = __shfl_sync(0xffffffffu, pre, 31);
    unsigned excl = pre - (unsigned)cnt;

    unsigned base = 0;
    if (lane == 31 && warptotal)
        base = atomicAdd(&g_npairs, 2 * (int)warptotal);
    base = __shfl_sync(0xffffffffu, base, 31);

    for (int j = 0; j < cnt; ++j) {
        int pos = (int)base + 2 * ((int)excl + j);
        int k  = kk[j];
        int nb = nbv[j];
        g_pairs[pos]     = make_int2((i  << 5) | k,        nb);
        g_pairs[pos + 1] = make_int2((nb << 5) | (26 - k), i);
    }
}

__device__ __forceinline__ void fma2(unsigned long long& acc, float f,
                                     unsigned long long wv) {
    unsigned long long fv2;
    asm("mov.b64 %0, {%1, %1};" : "=l"(fv2) : "f"(f));
    asm("fma.rn.f32x2 %0, %1, %2, %3;" : "=l"(acc) : "l"(fv2), "l"(wv), "l"(acc));
}

// Center matvec, software-pipelined persistent form. ONE 8-warp block per
// SM (half the RF) so chain blocks co-reside (R15 measured optimum).
__global__ void __launch_bounds__(256) center_kernel(
    const float* __restrict__ feat, const float* __restrict__ w,
    float* __restrict__ out, int n)
{
    __shared__ float4 sf[2][TILE * (C_IN / 4)];

    int tid   = threadIdx.x;
    int lane  = tid & 31;
    int wslot = tid >> 5;

    const float* w13 = w + KCENTER * C_IN * C_OUT;
    unsigned long long wreg[C_IN];
    #pragma unroll
    for (int c = 0; c < C_IN; ++c)
        wreg[c] = ((const unsigned long long*)w13)[c * 32 + lane];

    const float4* featv = (const float4*)feat;
    long maxf4 = (long)n * (C_IN / 4) - 1;
    int ntiles = (n + TILE - 1) / TILE;

    int t = blockIdx.x;
    float4 r0, r1;
    if (t < ntiles) {
        long base = (long)t * (TILE * C_IN / 4);
        long i0 = base + tid;       if (i0 > maxf4) i0 = maxf4;
        long i1 = base + tid + 256; if (i1 > maxf4) i1 = maxf4;
        r0 = featv[i0];
        r1 = featv[i1];
    }

    int buf = 0;
    for (; t < ntiles; t += gridDim.x) {
        sf[buf][tid]       = r0;
        sf[buf][tid + 256] = r1;
        __syncthreads();

        int tn = t + gridDim.x;
        if (tn < ntiles) {
            long base = (long)tn * (TILE * C_IN / 4);
            long i0 = base + tid;       if (i0 > maxf4) i0 = maxf4;
            long i1 = base + tid + 256; if (i1 > maxf4) i1 = maxf4;
            r0 = featv[i0];
            r1 = featv[i1];
        }

        int p0 = wslot * 8;
        #pragma unroll
        for (int pp = 0; pp < 8; ++pp) {
            int i = t * TILE + p0 + pp;
            if (i >= n) break;
            const float4* frow = &sf[buf][(p0 + pp) * (C_IN / 4)];
            unsigned long long acc0, acc1, acc2, acc3;
            asm("mov.b64 %0, {%1, %1};" : "=l"(acc0) : "f"(0.0f));
            asm("mov.b64 %0, {%1, %1};" : "=l"(acc1) : "f"(0.0f));
            asm("mov.b64 %0, {%1, %1};" : "=l"(acc2) : "f"(0.0f));
            asm("mov.b64 %0, {%1, %1};" : "=l"(acc3) : "f"(0.0f));
            #pragma unroll
            for (int c4 = 0; c4 < C_IN / 4; ++c4) {
                float4 fv = frow[c4];                // broadcast LDS.128
                fma2(acc0, fv.x, wreg[c4 * 4 + 0]);
                fma2(acc1, fv.y, wreg[c4 * 4 + 1]);
                fma2(acc2, fv.z, wreg[c4 * 4 + 2]);
                fma2(acc3, fv.w, wreg[c4 * 4 + 3]);
            }
            unsigned long long s01, s23, s;
            asm("add.rn.f32x2 %0, %1, %2;" : "=l"(s01) : "l"(acc0), "l"(acc1));
            asm("add.rn.f32x2 %0, %1, %2;" : "=l"(s23) : "l"(acc2), "l"(acc3));
            asm("add.rn.f32x2 %0, %1, %2;" : "=l"(s)   : "l"(s01),  "l"(s23));
            ((unsigned long long*)out)[(size_t)i * 32 + lane] = s;   // STG.64
        }
        __syncthreads();
        buf ^= 1;
    }
}

// Rare neighbor contributions. 2 pairs/warp-iteration; ALL 16 feature
// float4 loads preloaded into registers before any FMA (MLP=16).
__global__ void __launch_bounds__(128, 4) pairs_kernel(
    const float* __restrict__ feat,
    const float* __restrict__ w,
    float* __restrict__ out)
{
    int lane   = threadIdx.x & 31;
    int warp_g = (blockIdx.x * blockDim.x + threadIdx.x) >> 5;
    int nwarps = (gridDim.x * blockDim.x) >> 5;
    int np = g_npairs;

    for (int p = warp_g * 2; p < np; p += nwarps * 2) {
        int4 pq = ((const int4*)g_pairs)[p >> 1];
        bool has1 = (p + 1) < np;

        const float4* f0v = (const float4*)(feat + (size_t)pq.y * C_IN);
        const float4* f1v = (const float4*)(feat + (size_t)(has1 ? pq.w : pq.y) * C_IN);

        float4 f0[8], f1[8];
        #pragma unroll
        for (int c4 = 0; c4 < 8; ++c4) f0[c4] = f0v[c4];
        #pragma unroll
        for (int c4 = 0; c4 < 8; ++c4) f1[c4] = f1v[c4];

        const unsigned long long* wk0 =
            (const unsigned long long*)(w + (size_t)(pq.x & 31) * C_IN * C_OUT);
        const unsigned long long* wk1 =
            (const unsigned long long*)(w + (size_t)(pq.z & 31) * C_IN * C_OUT);

        unsigned long long a0, a1, b0, b1;
        asm("mov.b64 %0, {%1, %1};" : "=l"(a0) : "f"(0.0f));
        asm("mov.b64 %0, {%1, %1};" : "=l"(a1) : "f"(0.0f));
        asm("mov.b64 %0, {%1, %1};" : "=l"(b0) : "f"(0.0f));
        asm("mov.b64 %0, {%1, %1};" : "=l"(b1) : "f"(0.0f));

        #pragma unroll
        for (int c4 = 0; c4 < 8; ++c4) {
            fma2(a0, f0[c4].x, wk0[(c4 * 4 + 0) * 32 + lane]);
            fma2(a1, f0[c4].y, wk0[(c4 * 4 + 1) * 32 + lane]);
            fma2(a0, f0[c4].z, wk0[(c4 * 4 + 2) * 32 + lane]);
            fma2(a1, f0[c4].w, wk0[(c4 * 4 + 3) * 32 + lane]);
            fma2(b0, f1[c4].x, wk1[(c4 * 4 + 0) * 32 + lane]);
            fma2(b1, f1[c4].y, wk1[(c4 * 4 + 1) * 32 + lane]);
            fma2(b0, f1[c4].z, wk1[(c4 * 4 + 2) * 32 + lane]);
            fma2(b1, f1[c4].w, wk1[(c4 * 4 + 3) * 32 + lane]);
        }

        unsigned long long sa, sb;
        asm("add.rn.f32x2 %0, %1, %2;" : "=l"(sa) : "l"(a0), "l"(a1));
        asm("add.rn.f32x2 %0, %1, %2;" : "=l"(sb) : "l"(b0), "l"(b1));
        float sa0, sa1, sb0, sb1;
        asm("mov.b64 {%0, %1}, %2;" : "=f"(sa0), "=f"(sa1) : "l"(sa));
        asm("mov.b64 {%0, %1}, %2;" : "=f"(sb0), "=f"(sb1) : "l"(sb));

        int i0 = pq.x >> 5;
        atomicAdd(&out[(size_t)i0 * C_OUT + 2 * lane],     sa0);
        atomicAdd(&out[(size_t)i0 * C_OUT + 2 * lane + 1], sa1);
        if (has1) {
            int i1 = pq.z >> 5;
            atomicAdd(&out[(size_t)i1 * C_OUT + 2 * lane],     sb0);
            atomicAdd(&out[(size_t)i1 * C_OUT + 2 * lane + 1], sb1);
        }
    }
}

extern "C" void kernel_launch(void* const* d_in, const int* in_sizes, int n_in,
                              void* d_out, int out_size) {
    const float* feat = (const float*)d_in[0];
    const int*   idx  = (const int*)d_in[1];
    const float* w    = (const float*)d_in[2];
    float* out = (float*)d_out;

    int n = in_sizes[0] / C_IN;

    // Fork: center on high-priority side stream, one 8-warp block per SM;
    // chain blocks co-reside in the remaining half of each SM's RF.
    cudaEventRecord(g_ev_fork, 0);
    cudaStreamWaitEvent(g_s1, g_ev_fork, 0);
    center_kernel<<<148, 256, 0, g_s1>>>(feat, w, out, n);
    cudaEventRecord(g_ev_join, g_s1);

    clear_bitmap_kernel<<<(NWORDS / 4 + 255) / 256, 256>>>();
    scatter_kernel<<<(n + 255) / 256, 256>>>(idx, n);
    probe_kernel<<<(n * 5 + 255) / 256, 256>>>(idx, n);

    // Join: pairs needs both probe's pair list and center's stores.
    cudaStreamWaitEvent(0, g_ev_join, 0);
    pairs_kernel<<<1184, 128>>>(feat, w, out);
}